// round 11
// baseline (speedup 1.0000x reference)
#include <cuda_runtime.h>
#include <cstdint>

// LatticeSnake: B=32, L=512, W=9. Output [B, L, 9,9,9, 1] fp32 (48 MB).
// Doubled walk coords (the 2(L-1) grid offset cancels):
//   residue j:   p = 2*idx[j],         v = acids[j]*mask[j]
//   midpoint k:  p = idx[k]+idx[k+1],  v = (acids[k]+acids[k+1]+1)*mask[k+1]
//   voxel (i,r): value = sum of points at p == 2*idx[i] + r - 4
//
// R11: two kernels.
//   K1 (tiny): per batch, precompute all 1023 snake points as packed int4
//      (px,py,pz,value_bits) into a __device__ scratch (L2-resident).
//      Slot 1023 = far sentinel -> main scan needs no bounds check.
//   K2 (main): per 16-window group: zero 28.7KB grid, warp0 bbox (from
//      residue points), scan = 4 coalesced LDG.128 rounds + bbox test +
//      rare smem atomic, then R8-style gather (relOff reuse, LDS+STG.32).
//      No staging, 2 barriers, 7 CTAs/SM -> whole grid in one wave.

#define LS_L    512
#define LS_W    9
#define LS_W3   729
#define LS_R    16               // windows per CTA
#define LS_NT   256
#define LS_NG   (LS_L / LS_R)    // 32 groups per batch
#define LS_MP   1024             // padded point count per batch
#define GRID_F  7168             // >= worst-case vol 19^3 = 6859

__device__ int4 g_points[64 * LS_MP];   // packed snake points (scratch)

// ---------------- Kernel 1: build snake points ----------------
__global__ __launch_bounds__(512)
void ls_points_kernel(const float* __restrict__ acids,
                      const float* __restrict__ mask,
                      const int*   __restrict__ idx)
{
    __shared__ alignas(16) int   sidx[LS_L * 3];
    __shared__ alignas(16) float sA[LS_L];
    __shared__ alignas(16) float sM[LS_L];

    const int b   = blockIdx.x;
    const int tid = threadIdx.x;
    const int*   gi = idx   + (size_t)b * LS_L * 3;
    const float* ga = acids + (size_t)b * LS_L;
    const float* gm = mask  + (size_t)b * LS_L;

    {
        const int4* gi4 = reinterpret_cast<const int4*>(gi);
        int4* s4 = reinterpret_cast<int4*>(sidx);
        for (int e = tid; e < (LS_L * 3) / 4; e += 512) s4[e] = gi4[e];
        const float4* ga4 = reinterpret_cast<const float4*>(ga);
        const float4* gm4 = reinterpret_cast<const float4*>(gm);
        float4* a4 = reinterpret_cast<float4*>(sA);
        float4* m4 = reinterpret_cast<float4*>(sM);
        if (tid < LS_L / 4) { a4[tid] = ga4[tid]; m4[tid] = gm4[tid]; }
    }
    __syncthreads();

    int4* gp = g_points + b * LS_MP;

    // round 0: residues (j = tid, 0..511)
    {
        const int jj = 3 * tid;
        gp[tid] = make_int4(2 * sidx[jj + 0], 2 * sidx[jj + 1],
                            2 * sidx[jj + 2],
                            __float_as_int(sA[tid] * sM[tid]));
    }
    // round 1: midpoints (k = tid, 0..510) + sentinel at 1023
    {
        const int j = tid + LS_L;
        if (tid < LS_L - 1) {
            const int jj = 3 * tid;
            gp[j] = make_int4(sidx[jj + 0] + sidx[jj + 3],
                              sidx[jj + 1] + sidx[jj + 4],
                              sidx[jj + 2] + sidx[jj + 5],
                              __float_as_int((sA[tid] + sA[tid + 1] + 1.0f)
                                             * sM[tid + 1]));
        } else if (tid == LS_L - 1) {
            gp[j] = make_int4(1 << 28, 1 << 28, 1 << 28, 0);  // sentinel
        }
    }
}

// ---------------- Kernel 2: main (grid gather) ----------------
__global__ __launch_bounds__(LS_NT, 7)
void lattice_snake_kernel(float* __restrict__ out)
{
    __shared__ alignas(16) float grid[GRID_F];   // 28672 B
    __shared__ int sAw[LS_R];                    // per-window grid base cell
    __shared__ int sBB[6];                       // gxl,gyl,gzl,sx,sy,sz

    const int b   = blockIdx.x >> 5;            // / LS_NG
    const int g   = blockIdx.x & (LS_NG - 1);
    const int i0  = g * LS_R;
    const int tid = threadIdx.x;

    const int4* gp = g_points + b * LS_MP;
    float* gout = out + (size_t)(b * LS_L + i0) * LS_W3;

    // ---- zero grid ----
    {
        float4* g4 = reinterpret_cast<float4*>(grid);
        const float4 z = make_float4(0.f, 0.f, 0.f, 0.f);
        #pragma unroll
        for (int e = tid; e < GRID_F / 4; e += LS_NT) g4[e] = z;
    }

    // ---- warp 0: bbox over 16 centers (residue points) + window bases ----
    if (tid < 32) {
        const int r = tid & 15;                  // lanes 16-31 duplicate
        const int4 c = gp[i0 + r];               // residue point = 2*idx
        int xmin = c.x, xmax = c.x, ymin = c.y, ymax = c.y,
            zmin = c.z, zmax = c.z;
        #pragma unroll
        for (int d = 8; d >= 1; d >>= 1) {
            xmin = min(xmin, __shfl_xor_sync(0xffffffffu, xmin, d));
            xmax = max(xmax, __shfl_xor_sync(0xffffffffu, xmax, d));
            ymin = min(ymin, __shfl_xor_sync(0xffffffffu, ymin, d));
            ymax = max(ymax, __shfl_xor_sync(0xffffffffu, ymax, d));
            zmin = min(zmin, __shfl_xor_sync(0xffffffffu, zmin, d));
            zmax = max(zmax, __shfl_xor_sync(0xffffffffu, zmax, d));
        }
        const int syv = ymax - ymin + 9;
        const int szv = zmax - zmin + 9;
        if (tid < 16)
            sAw[tid] = ((c.x - xmin) * syv + (c.y - ymin)) * szv + (c.z - zmin);
        if (tid == 0) {
            sBB[0] = xmin - 4; sBB[1] = ymin - 4; sBB[2] = zmin - 4;
            sBB[3] = xmax - xmin + 9; sBB[4] = syv; sBB[5] = szv;
        }
    }
    __syncthreads();

    const int gxl = sBB[0], gyl = sBB[1], gzl = sBB[2];
    const int sx  = sBB[3], sy  = sBB[4], sz  = sBB[5];

    // ---- scan 1024 packed points (incl. sentinel); coalesced LDG.128 ----
    #pragma unroll
    for (int rnd = 0; rnd < LS_MP / LS_NT; rnd++) {
        const int4 p = gp[rnd * LS_NT + tid];
        const unsigned ux = (unsigned)(p.x - gxl);
        const unsigned uy = (unsigned)(p.y - gyl);
        const unsigned uz = (unsigned)(p.z - gzl);
        if (ux < (unsigned)sx && uy < (unsigned)sy && uz < (unsigned)sz)
            atomicAdd(&grid[(ux * sy + uy) * sz + uz], __int_as_float(p.w));
    }

    // per-thread voxel decomposition (reused across all 16 windows)
    int relOff0, relOff1, relOff2;
    {
        #pragma unroll
        for (int kk = 0; kk < 3; kk++) {
            const int lin = tid + kk * LS_NT;
            const int rx  = lin / 81;
            const int rem = lin - rx * 81;
            const int ry  = rem / 9;
            const int rz  = rem - ry * 9;
            const int off = (rx * sy + ry) * sz + rz;
            if (kk == 0) relOff0 = off;
            else if (kk == 1) relOff1 = off;
            else relOff2 = off;
        }
    }
    __syncthreads();   // grid complete

    // ---- gather: voxel = one LDS + one coalesced STG.32 ----
    const bool k2ok = tid < (LS_W3 - 2 * LS_NT);   // 217
    #pragma unroll
    for (int w = 0; w < LS_R; w++) {
        const int Aw = sAw[w];                     // broadcast LDS
        float* gw = gout + w * LS_W3;
        gw[tid]             = grid[Aw + relOff0];
        gw[tid + LS_NT]     = grid[Aw + relOff1];
        if (k2ok) gw[tid + 2 * LS_NT] = grid[Aw + relOff2];
    }
}

extern "C" void kernel_launch(void* const* d_in, const int* in_sizes, int n_in,
                              void* d_out, int out_size)
{
    const float* acids = (const float*)d_in[0];   // [B, L]
    const float* mask  = (const float*)d_in[1];   // [B, L]
    const int*   idx   = (const int*)  d_in[2];   // [B, L, 3]
    float*       out   = (float*)d_out;           // [B, L, 9,9,9, 1]

    const int nB = in_sizes[0] / LS_L;            // 32
    ls_points_kernel<<<nB, 512>>>(acids, mask, idx);
    lattice_snake_kernel<<<nB * LS_NG, LS_NT>>>(out);
}

// round 12
// speedup vs baseline: 1.0152x; 1.0152x over previous
#include <cuda_runtime.h>
#include <cstdint>

// LatticeSnake: B=32, L=512, W=9. Output [B, L, 9,9,9, 1] fp32 (48 MB).
// Doubled walk coords (the 2(L-1) grid offset cancels):
//   residue j:   p = 2*idx[j],         v = acids[j]*mask[j]
//   midpoint k:  p = idx[k]+idx[k+1],  v = (acids[k]+acids[k+1)+1)*mask[k+1]
//   voxel (i,r): value = sum of points at p == 2*idx[i] + r - 4
//
// R12: overlap-first design.
//   K1 (32 CTAs x 512): packs all 1023 snake points (int4 px,py,pz,val) AND
//      per-8-window-group meta (bbox mins, dims, 8 window base cells) into
//      __device__ scratch. 512 threads = 64 groups x 8 windows exactly.
//   K2 (2048 CTAs x 128, 16 CTAs/SM => single wave, 14/SM):
//      grid is provably <= (2a+9)(2b+9)(2c+9), a+b+c<=7 -> 2535 floats
//      (10.2 KB smem). Phases: [zero + meta load] -> bar ->
//      [8 coalesced LDG.128 scan rounds + rare smem atomic] -> bar ->
//      [gather: LDS + coalesced STG.32]. No serial bbox phase, 2 barriers.

#define LS_L    512
#define LS_W    9
#define LS_W3   729
#define LS_R    8                // windows per K2 CTA
#define LS_NT   128
#define LS_NG   (LS_L / LS_R)    // 64 groups per batch
#define LS_MP   1024             // padded point count per batch
#define GRID_F  2560             // >= worst-case vol 15*13*13 = 2535

__device__ int4 g_points[64 * LS_MP];        // packed snake points
__device__ int  g_meta[64 * LS_NG * 16];     // per group: bbox(6) + base[8]

// ---------------- Kernel 1: points + per-group meta ----------------
__global__ __launch_bounds__(512)
void ls_prep_kernel(const float* __restrict__ acids,
                    const float* __restrict__ mask,
                    const int*   __restrict__ idx)
{
    __shared__ alignas(16) int   sidx[LS_L * 3];
    __shared__ alignas(16) float sA[LS_L];
    __shared__ alignas(16) float sM[LS_L];

    const int b   = blockIdx.x;
    const int tid = threadIdx.x;
    const int*   gi = idx   + (size_t)b * LS_L * 3;
    const float* ga = acids + (size_t)b * LS_L;
    const float* gm = mask  + (size_t)b * LS_L;

    {
        const int4* gi4 = reinterpret_cast<const int4*>(gi);
        int4* s4 = reinterpret_cast<int4*>(sidx);
        for (int e = tid; e < (LS_L * 3) / 4; e += 512) s4[e] = gi4[e];
        const float4* ga4 = reinterpret_cast<const float4*>(ga);
        const float4* gm4 = reinterpret_cast<const float4*>(gm);
        float4* a4 = reinterpret_cast<float4*>(sA);
        float4* m4 = reinterpret_cast<float4*>(sM);
        if (tid < LS_L / 4) { a4[tid] = ga4[tid]; m4[tid] = gm4[tid]; }
    }
    __syncthreads();

    int4* gp = g_points + b * LS_MP;

    // residues (j = tid)
    {
        const int jj = 3 * tid;
        gp[tid] = make_int4(2 * sidx[jj + 0], 2 * sidx[jj + 1],
                            2 * sidx[jj + 2],
                            __float_as_int(sA[tid] * sM[tid]));
    }
    // midpoints (k = tid) + sentinel at slot 1023
    {
        const int j = tid + LS_L;
        if (tid < LS_L - 1) {
            const int jj = 3 * tid;
            gp[j] = make_int4(sidx[jj + 0] + sidx[jj + 3],
                              sidx[jj + 1] + sidx[jj + 4],
                              sidx[jj + 2] + sidx[jj + 5],
                              __float_as_int((sA[tid] + sA[tid + 1] + 1.0f)
                                             * sM[tid + 1]));
        } else if (tid == LS_L - 1) {
            gp[j] = make_int4(1 << 28, 1 << 28, 1 << 28, 0);  // sentinel
        }
    }

    // per-group meta: thread = (group g = tid>>3, window r = tid&7)
    {
        const int g  = tid >> 3;
        const int r  = tid & 7;
        const int jj = 3 * (g * LS_R + r);
        const int cx = 2 * sidx[jj + 0];
        const int cy = 2 * sidx[jj + 1];
        const int cz = 2 * sidx[jj + 2];
        int xmin = cx, xmax = cx, ymin = cy, ymax = cy, zmin = cz, zmax = cz;
        #pragma unroll
        for (int d = 4; d >= 1; d >>= 1) {   // segmented over 8 lanes
            xmin = min(xmin, __shfl_xor_sync(0xffffffffu, xmin, d));
            xmax = max(xmax, __shfl_xor_sync(0xffffffffu, xmax, d));
            ymin = min(ymin, __shfl_xor_sync(0xffffffffu, ymin, d));
            ymax = max(ymax, __shfl_xor_sync(0xffffffffu, ymax, d));
            zmin = min(zmin, __shfl_xor_sync(0xffffffffu, zmin, d));
            zmax = max(zmax, __shfl_xor_sync(0xffffffffu, zmax, d));
        }
        const int syv = ymax - ymin + 9;
        const int szv = zmax - zmin + 9;
        int* m = g_meta + (b * LS_NG + g) * 16;
        m[6 + r] = ((cx - xmin) * syv + (cy - ymin)) * szv + (cz - zmin);
        if (r == 0) {
            m[0] = xmin - 4; m[1] = ymin - 4; m[2] = zmin - 4;
            m[3] = xmax - xmin + 9; m[4] = syv; m[5] = szv;
        }
    }
}

// ---------------- Kernel 2: main (grid gather) ----------------
__global__ __launch_bounds__(LS_NT, 16)
void lattice_snake_kernel(float* __restrict__ out)
{
    __shared__ alignas(16) float grid[GRID_F];   // 10240 B
    __shared__ int sMeta[16];                    // bbox(6) + base[8]

    const int b   = blockIdx.x >> 6;            // / LS_NG
    const int g   = blockIdx.x & (LS_NG - 1);
    const int tid = threadIdx.x;

    const int4* gp = g_points + b * LS_MP;
    float* gout = out + (size_t)(b * LS_L + g * LS_R) * LS_W3;

    // meta load (overlaps zeroing; LDG latency hidden behind STS)
    if (tid < 14) sMeta[tid] = g_meta[(b * LS_NG + g) * 16 + tid];

    // ---- zero grid (640 float4 / 128 thr = 5 each) ----
    {
        float4* g4 = reinterpret_cast<float4*>(grid);
        const float4 z = make_float4(0.f, 0.f, 0.f, 0.f);
        #pragma unroll
        for (int e = tid; e < GRID_F / 4; e += LS_NT) g4[e] = z;
    }
    __syncthreads();

    const int gxl = sMeta[0], gyl = sMeta[1], gzl = sMeta[2];
    const int sx  = sMeta[3], sy  = sMeta[4], sz  = sMeta[5];

    // ---- scan 1024 packed points; 8 coalesced LDG.128 rounds (MLP 8) ----
    #pragma unroll
    for (int rnd = 0; rnd < LS_MP / LS_NT; rnd++) {
        const int4 p = gp[rnd * LS_NT + tid];
        const unsigned ux = (unsigned)(p.x - gxl);
        const unsigned uy = (unsigned)(p.y - gyl);
        const unsigned uz = (unsigned)(p.z - gzl);
        if (ux < (unsigned)sx && uy < (unsigned)sy && uz < (unsigned)sz)
            atomicAdd(&grid[(ux * sy + uy) * sz + uz], __int_as_float(p.w));
    }

    // per-thread voxel decomposition (6 rounds of 128 cover 729)
    int ro[6];
    #pragma unroll
    for (int k = 0; k < 6; k++) {
        const int lin = tid + k * LS_NT;
        const int rx  = lin / 81;
        const int rem = lin - rx * 81;
        const int ry  = rem / 9;
        const int rz  = rem - ry * 9;
        ro[k] = (rx * sy + ry) * sz + rz;
    }
    __syncthreads();   // grid complete

    // ---- gather: voxel = one LDS + one coalesced STG.32 ----
    const bool k5ok = tid < (LS_W3 - 5 * LS_NT);   // 89
    #pragma unroll
    for (int w = 0; w < LS_R; w++) {
        const int Aw = sMeta[6 + w];               // broadcast LDS
        float* gw = gout + w * LS_W3;
        gw[tid]              = grid[Aw + ro[0]];
        gw[tid + 1 * LS_NT]  = grid[Aw + ro[1]];
        gw[tid + 2 * LS_NT]  = grid[Aw + ro[2]];
        gw[tid + 3 * LS_NT]  = grid[Aw + ro[3]];
        gw[tid + 4 * LS_NT]  = grid[Aw + ro[4]];
        if (k5ok) gw[tid + 5 * LS_NT] = grid[Aw + ro[5]];
    }
}

extern "C" void kernel_launch(void* const* d_in, const int* in_sizes, int n_in,
                              void* d_out, int out_size)
{
    const float* acids = (const float*)d_in[0];   // [B, L]
    const float* mask  = (const float*)d_in[1];   // [B, L]
    const int*   idx   = (const int*)  d_in[2];   // [B, L, 3]
    float*       out   = (float*)d_out;           // [B, L, 9,9,9, 1]

    const int nB = in_sizes[0] / LS_L;            // 32
    ls_prep_kernel<<<nB, 512>>>(acids, mask, idx);
    lattice_snake_kernel<<<nB * LS_NG, LS_NT>>>(out);
}